// round 13
// baseline (speedup 1.0000x reference)
#include <cuda_runtime.h>

// Range_Fourier_Net: y = DFT_512(x) per row, complex, output stacked (re, im).
// Radix-8^3 FFT, exact twiddles from row 1 of the provided DFT weight matrix.
//
// R13 = R12 (warp-autonomous: one warp per row pair, each thread owns columns
// t and t+32, intra-warp exchanges, __syncwarp only) with:
//  - guards removed (shape-exact grid + benign clamp) -> no per-load SELs
//  - float2 scratch reused sequentially for row A then row B -> 4.2 KB/warp
//    (smem was the occupancy cap at 8.3 KB/warp)
//  - launch_bounds(128,6): 85-reg ceiling, 6 CTAs = 24 warps/SM target
//  - stage-2 twiddle factor chain computed once for all four arrays

#define WARPS_PER_CTA 4
#define CTA_THREADS (WARPS_PER_CTA * 32)
#define P1 64
#define P2 65
#define BUF_LEN 520   // max(7*64+63, 7*65+63)+1

__device__ __forceinline__ float2 cadd(float2 a, float2 b) {
    return make_float2(a.x + b.x, a.y + b.y);
}
__device__ __forceinline__ float2 csub(float2 a, float2 b) {
    return make_float2(a.x - b.x, a.y - b.y);
}
__device__ __forceinline__ float2 cmul(float2 a, float2 b) {
    return make_float2(fmaf(a.x, b.x, -a.y * b.y), fmaf(a.x, b.y, a.y * b.x));
}
// multiply by -i  (W8^2)
__device__ __forceinline__ float2 mul_mi(float2 a) { return make_float2(a.y, -a.x); }

// Natural-order 8-point DFT: v[h] = sum_j v_in[j] * W8^{j*h}, W8 = exp(-i*pi/4)
__device__ __forceinline__ void dft8(float2 v[8]) {
    float2 e0 = v[0], e1 = v[2], e2 = v[4], e3 = v[6];
    float2 o0 = v[1], o1 = v[3], o2 = v[5], o3 = v[7];
    float2 t0 = cadd(e0, e2), t1 = csub(e0, e2);
    float2 t2 = cadd(e1, e3), t3 = mul_mi(csub(e1, e3));
    float2 E0 = cadd(t0, t2), E2 = csub(t0, t2);
    float2 E1 = cadd(t1, t3), E3 = csub(t1, t3);
    float2 s0 = cadd(o0, o2), s1 = csub(o0, o2);
    float2 s2 = cadd(o1, o3), s3 = mul_mi(csub(o1, o3));
    float2 O0 = cadd(s0, s2), O2 = csub(s0, s2);
    float2 O1 = cadd(s1, s3), O3 = csub(s1, s3);
    const float S = 0.70710678118654752440f;
    float2 W1 = make_float2(S * (O1.x + O1.y), S * (O1.y - O1.x));
    float2 W2 = mul_mi(O2);
    float2 W3 = make_float2(S * (O3.y - O3.x), -S * (O3.x + O3.y));
    v[0] = cadd(E0, O0); v[4] = csub(E0, O0);
    v[1] = cadd(E1, W1); v[5] = csub(E1, W1);
    v[2] = cadd(E2, W2); v[6] = csub(E2, W2);
    v[3] = cadd(E3, W3); v[7] = csub(E3, W3);
}

// apply base^h (h=1..7) to TWO arrays sharing the same twiddle base
__device__ __forceinline__ void twiddle_chain2(float2 u[8], float2 v[8], float2 base) {
    float2 f = base;
    #pragma unroll
    for (int h = 1; h < 8; h++) {
        u[h] = cmul(u[h], f);
        v[h] = cmul(v[h], f);
        if (h < 7) f = cmul(f, base);
    }
}

// apply base^h to FOUR arrays sharing one base (stage 2): f chain computed once
__device__ __forceinline__ void twiddle_chain4(float2 u0[8], float2 u1[8],
                                               float2 v0[8], float2 v1[8], float2 base) {
    float2 f = base;
    #pragma unroll
    for (int h = 1; h < 8; h++) {
        u0[h] = cmul(u0[h], f);
        u1[h] = cmul(u1[h], f);
        v0[h] = cmul(v0[h], f);
        v1[h] = cmul(v1[h], f);
        if (h < 7) f = cmul(f, base);
    }
}

// full intra-warp digit-reversal pipeline for ONE row (both column sets),
// using the shared float2 scratch. On entry: a0/a1 = stage-1 outputs
// (already twiddled). On exit: a0/a1 = final DFT values for cols c0/c1.
__device__ __forceinline__ void exchange_and_finish(
    float2 a0[8], float2 a1[8], float2* __restrict__ buf,
    int c0, int c1, int j0, int q0, int q1, float2 base2)
{
    // exchange 1 store: p = h*64 + c  (STS.64, conflict-free)
    #pragma unroll
    for (int h = 0; h < 8; h++) {
        buf[h * P1 + c0] = a0[h];
        buf[h * P1 + c1] = a1[h];
    }
    __syncwarp();
    // gather: column (q, j0) reads p = q*64 + j1*8 + j0
    #pragma unroll
    for (int j1 = 0; j1 < 8; j1++) {
        a0[j1] = buf[q0 * P1 + j1 * 8 + j0];
        a1[j1] = buf[q1 * P1 + j1 * 8 + j0];
    }
    __syncwarp();

    // Stage 2: radix-8 over j1; twiddle (W^(8*j0))^h1
    dft8(a0); dft8(a1);
    twiddle_chain2(a0, a1, base2);

    // exchange 2 store: p = j0*65 + h1*8 + q
    #pragma unroll
    for (int h = 0; h < 8; h++) {
        buf[j0 * P2 + h * 8 + q0] = a0[h];
        buf[j0 * P2 + h * 8 + q1] = a1[h];
    }
    __syncwarp();
    #pragma unroll
    for (int j = 0; j < 8; j++) {
        a0[j] = buf[j * P2 + c0];
        a1[j] = buf[j * P2 + c1];
    }
    __syncwarp();

    // Stage 3: radix-8 over j0
    dft8(a0); dft8(a1);
}

__global__ __launch_bounds__(CTA_THREADS, 6)
void fft512_kernel(const float* __restrict__ xre, const float* __restrict__ xim,
                   const float* __restrict__ wre, const float* __restrict__ wim,
                   float2* __restrict__ out, int nrows)
{
    // one float2 scratch per warp, reused for row A then row B
    __shared__ float2 buf[WARPS_PER_CTA][BUF_LEN];   // 4*520*8 = 16,640 B

    const int tid  = threadIdx.x;
    const int wid  = tid >> 5;
    const int lane = tid & 31;
    const int c0 = lane;
    const int c1 = lane + 32;
    const int j0 = lane & 7;
    const int q0 = lane >> 3;
    const int q1 = q0 + 4;

    // grid covers rows exactly (nrows % 8 == 0); clamp is benign (duplicate
    // writers would write identical data), removes per-load predication.
    int rowA = (blockIdx.x * WARPS_PER_CTA + wid) * 2;
    if (rowA > nrows - 2) rowA = nrows - 2;
    const int rowB = rowA + 1;

    // exact base twiddles from DFT-matrix row 1: W512^m = w[512+m]
    const float2 base1a = make_float2(__ldg(&wre[512 + c0]), __ldg(&wim[512 + c0]));
    const float2 base1b = make_float2(__ldg(&wre[512 + c1]), __ldg(&wim[512 + c1]));
    const float2 base2  = make_float2(__ldg(&wre[512 + 8 * j0]), __ldg(&wim[512 + 8 * j0]));

    // ---- front-batched loads: 64 unguarded LDGs in flight ----
    float2 a0[8], a1[8], b0[8], b1[8];
    {
        const float* xrA = xre + (size_t)rowA * 512;
        const float* xiA = xim + (size_t)rowA * 512;
        const float* xrB = xrA + 512;
        const float* xiB = xiA + 512;
        float a0r[8], a0i[8], a1r[8], a1i[8];
        float b0r[8], b0i[8], b1r[8], b1i[8];
        #pragma unroll
        for (int j = 0; j < 8; j++) a0r[j] = xrA[c0 + 64 * j];
        #pragma unroll
        for (int j = 0; j < 8; j++) a1r[j] = xrA[c1 + 64 * j];
        #pragma unroll
        for (int j = 0; j < 8; j++) a0i[j] = xiA[c0 + 64 * j];
        #pragma unroll
        for (int j = 0; j < 8; j++) a1i[j] = xiA[c1 + 64 * j];
        #pragma unroll
        for (int j = 0; j < 8; j++) b0r[j] = xrB[c0 + 64 * j];
        #pragma unroll
        for (int j = 0; j < 8; j++) b1r[j] = xrB[c1 + 64 * j];
        #pragma unroll
        for (int j = 0; j < 8; j++) b0i[j] = xiB[c0 + 64 * j];
        #pragma unroll
        for (int j = 0; j < 8; j++) b1i[j] = xiB[c1 + 64 * j];
        #pragma unroll
        for (int j = 0; j < 8; j++) {
            a0[j] = make_float2(a0r[j], a0i[j]);
            a1[j] = make_float2(a1r[j], a1i[j]);
            b0[j] = make_float2(b0r[j], b0i[j]);
            b1[j] = make_float2(b1r[j], b1i[j]);
        }
    }

    // ---- Stage 1 (all four arrays): radix-8 over j2; twiddle (W^c)^h2 ----
    dft8(a0); dft8(b0); twiddle_chain2(a0, b0, base1a);
    dft8(a1); dft8(b1); twiddle_chain2(a1, b1, base1b);

    // ---- Row A through the exchange pipeline, then store ----
    exchange_and_finish(a0, a1, buf[wid], c0, c1, j0, q0, q1, base2);
    {
        float2* orow = out + (size_t)rowA * 512;
        #pragma unroll
        for (int h0 = 0; h0 < 8; h0++) {
            orow[h0 * 64 + c0] = a0[h0];
            orow[h0 * 64 + c1] = a1[h0];
        }
    }

    // ---- Row B through the same scratch ----
    exchange_and_finish(b0, b1, buf[wid], c0, c1, j0, q0, q1, base2);
    {
        float2* orow = out + (size_t)rowB * 512;
        #pragma unroll
        for (int h0 = 0; h0 < 8; h0++) {
            orow[h0 * 64 + c0] = b0[h0];
            orow[h0 * 64 + c1] = b1[h0];
        }
    }
}

extern "C" void kernel_launch(void* const* d_in, const int* in_sizes, int n_in,
                              void* d_out, int out_size)
{
    const float* xre = (const float*)d_in[0];
    const float* xim = (const float*)d_in[1];
    const float* wre = (const float*)d_in[2];
    const float* wim = (const float*)d_in[3];
    float2* out = (float2*)d_out;

    const int nrows = in_sizes[0] / 512;            // 32768
    const int rows_per_cta = WARPS_PER_CTA * 2;     // 8
    const int grid = (nrows + rows_per_cta - 1) / rows_per_cta;   // 4096
    fft512_kernel<<<grid, CTA_THREADS>>>(xre, xim, wre, wim, out, nrows);
}

// round 14
// speedup vs baseline: 1.4022x; 1.4022x over previous
#include <cuda_runtime.h>

// Range_Fourier_Net: y = DFT_512(x) per row, complex, output stacked (re, im).
// Radix-8^3 FFT, exact twiddles from row 1 of the provided DFT weight matrix.
//
// R14 = R12 (warp-autonomous, one warp per row pair, float4-packed .128
// exchanges, __syncwarp only) with HALVED scratch via split exchanges:
// ex-1 gather for columns q0 (0..3) only needs store slots h=0..3, and q1
// needs h=4..7 -> run each exchange as two halves through a 264-entry float4
// buffer (4.2 KB/warp). Same STS/LDS.128 count as R12, +2 syncwarp/exchange.
// smem 16.9 KB/CTA -> occupancy now reg-limited; launch_bounds(128,6) = 85
// regs, 6 CTAs = 24 warps/SM (+50% vs R12).
//
// Bank analysis (.128, 8-lane phases, bank = 4p mod 32):
//  ex1 store  p = h*64+c        -> 4*lane            OK
//  ex1 gather p = q*64+j1*8+j0  -> 4*j0 (q const/ph) OK
//  ex2 store  p = j0*33+h*8+q   -> 4*j0+4q           OK
//  ex2 gather p = j*33+lane     -> 4*lane            OK

#define WARPS_PER_CTA 4
#define CTA_THREADS (WARPS_PER_CTA * 32)
#define P2 33
#define BUF_LEN 264   // max(4*64, 7*33+3*8+7+1) = max(256, 263) -> 264

__device__ __forceinline__ float2 cadd(float2 a, float2 b) {
    return make_float2(a.x + b.x, a.y + b.y);
}
__device__ __forceinline__ float2 csub(float2 a, float2 b) {
    return make_float2(a.x - b.x, a.y - b.y);
}
__device__ __forceinline__ float2 cmul(float2 a, float2 b) {
    return make_float2(fmaf(a.x, b.x, -a.y * b.y), fmaf(a.x, b.y, a.y * b.x));
}
// multiply by -i  (W8^2)
__device__ __forceinline__ float2 mul_mi(float2 a) { return make_float2(a.y, -a.x); }

// Natural-order 8-point DFT: v[h] = sum_j v_in[j] * W8^{j*h}, W8 = exp(-i*pi/4)
__device__ __forceinline__ void dft8(float2 v[8]) {
    float2 e0 = v[0], e1 = v[2], e2 = v[4], e3 = v[6];
    float2 o0 = v[1], o1 = v[3], o2 = v[5], o3 = v[7];
    float2 t0 = cadd(e0, e2), t1 = csub(e0, e2);
    float2 t2 = cadd(e1, e3), t3 = mul_mi(csub(e1, e3));
    float2 E0 = cadd(t0, t2), E2 = csub(t0, t2);
    float2 E1 = cadd(t1, t3), E3 = csub(t1, t3);
    float2 s0 = cadd(o0, o2), s1 = csub(o0, o2);
    float2 s2 = cadd(o1, o3), s3 = mul_mi(csub(o1, o3));
    float2 O0 = cadd(s0, s2), O2 = csub(s0, s2);
    float2 O1 = cadd(s1, s3), O3 = csub(s1, s3);
    const float S = 0.70710678118654752440f;
    float2 W1 = make_float2(S * (O1.x + O1.y), S * (O1.y - O1.x));
    float2 W2 = mul_mi(O2);
    float2 W3 = make_float2(S * (O3.y - O3.x), -S * (O3.x + O3.y));
    v[0] = cadd(E0, O0); v[4] = csub(E0, O0);
    v[1] = cadd(E1, W1); v[5] = csub(E1, W1);
    v[2] = cadd(E2, W2); v[6] = csub(E2, W2);
    v[3] = cadd(E3, W3); v[7] = csub(E3, W3);
}

// apply base^h (h=1..7) to TWO arrays sharing the same twiddle base
__device__ __forceinline__ void twiddle_chain2(float2 u[8], float2 v[8], float2 base) {
    float2 f = base;
    #pragma unroll
    for (int h = 1; h < 8; h++) {
        u[h] = cmul(u[h], f);
        v[h] = cmul(v[h], f);
        if (h < 7) f = cmul(f, base);
    }
}

__global__ __launch_bounds__(CTA_THREADS, 6)
void fft512_kernel(const float* __restrict__ xre, const float* __restrict__ xim,
                   const float* __restrict__ wre, const float* __restrict__ wim,
                   float2* __restrict__ out, int nrows)
{
    // per warp: float4 scratch; element = (Are, Aim, Bre, Bim)
    __shared__ float4 buf_s[WARPS_PER_CTA][BUF_LEN];   // 4*264*16 = 16,896 B

    const int tid  = threadIdx.x;
    const int wid  = tid >> 5;
    const int lane = tid & 31;
    const int c0 = lane;            // column set 0
    const int c1 = lane + 32;       // column set 1
    const int j0 = lane & 7;
    const int q0 = lane >> 3;       // 0..3
    float4* __restrict__ buf = buf_s[wid];

    const int rowA = (blockIdx.x * WARPS_PER_CTA + wid) * 2;
    const int rowB = rowA + 1;
    const bool actA = rowA < nrows;
    const bool actB = rowB < nrows;

    // exact base twiddles from DFT-matrix row 1: W512^m = w[512+m]
    const float2 base1a = make_float2(__ldg(&wre[512 + c0]), __ldg(&wim[512 + c0]));
    const float2 base1b = make_float2(__ldg(&wre[512 + c1]), __ldg(&wim[512 + c1]));
    const float2 base2  = make_float2(__ldg(&wre[512 + 8 * j0]), __ldg(&wim[512 + 8 * j0]));

    // ---- front-batched loads: 64 LDGs in flight per thread ----
    float2 a0[8], a1[8], b0[8], b1[8];
    {
        const float* xrA = xre + (size_t)rowA * 512;
        const float* xiA = xim + (size_t)rowA * 512;
        const float* xrB = xrA + 512;
        const float* xiB = xiA + 512;
        float a0r[8], a0i[8], a1r[8], a1i[8];
        float b0r[8], b0i[8], b1r[8], b1i[8];
        #pragma unroll
        for (int j = 0; j < 8; j++) a0r[j] = actA ? xrA[c0 + 64 * j] : 0.f;
        #pragma unroll
        for (int j = 0; j < 8; j++) a1r[j] = actA ? xrA[c1 + 64 * j] : 0.f;
        #pragma unroll
        for (int j = 0; j < 8; j++) a0i[j] = actA ? xiA[c0 + 64 * j] : 0.f;
        #pragma unroll
        for (int j = 0; j < 8; j++) a1i[j] = actA ? xiA[c1 + 64 * j] : 0.f;
        #pragma unroll
        for (int j = 0; j < 8; j++) b0r[j] = actB ? xrB[c0 + 64 * j] : 0.f;
        #pragma unroll
        for (int j = 0; j < 8; j++) b1r[j] = actB ? xrB[c1 + 64 * j] : 0.f;
        #pragma unroll
        for (int j = 0; j < 8; j++) b0i[j] = actB ? xiB[c0 + 64 * j] : 0.f;
        #pragma unroll
        for (int j = 0; j < 8; j++) b1i[j] = actB ? xiB[c1 + 64 * j] : 0.f;
        #pragma unroll
        for (int j = 0; j < 8; j++) {
            a0[j] = make_float2(a0r[j], a0i[j]);
            a1[j] = make_float2(a1r[j], a1i[j]);
            b0[j] = make_float2(b0r[j], b0i[j]);
            b1[j] = make_float2(b1r[j], b1i[j]);
        }
    }

    // ---- Stage 1: radix-8 over j2 (stride 64); twiddle (W^c)^h2 ----
    dft8(a0); dft8(b0); twiddle_chain2(a0, b0, base1a);
    dft8(a1); dft8(b1); twiddle_chain2(a1, b1, base1b);

    // ---- Exchange 1, half 0 (store h=0..3; gather column set c0) ----
    float2 na0[8], nb0[8], na1[8], nb1[8];
    #pragma unroll
    for (int h = 0; h < 4; h++) {
        buf[h * 64 + c0] = make_float4(a0[h].x, a0[h].y, b0[h].x, b0[h].y);
        buf[h * 64 + c1] = make_float4(a1[h].x, a1[h].y, b1[h].x, b1[h].y);
    }
    __syncwarp();
    #pragma unroll
    for (int j1 = 0; j1 < 8; j1++) {
        float4 u = buf[q0 * 64 + j1 * 8 + j0];
        na0[j1] = make_float2(u.x, u.y);
        nb0[j1] = make_float2(u.z, u.w);
    }
    __syncwarp();
    // ---- Exchange 1, half 1 (store h=4..7; gather column set c1) ----
    #pragma unroll
    for (int h = 4; h < 8; h++) {
        buf[(h - 4) * 64 + c0] = make_float4(a0[h].x, a0[h].y, b0[h].x, b0[h].y);
        buf[(h - 4) * 64 + c1] = make_float4(a1[h].x, a1[h].y, b1[h].x, b1[h].y);
    }
    __syncwarp();
    #pragma unroll
    for (int j1 = 0; j1 < 8; j1++) {
        float4 u = buf[q0 * 64 + j1 * 8 + j0];   // (q1-4) == q0
        na1[j1] = make_float2(u.x, u.y);
        nb1[j1] = make_float2(u.z, u.w);
    }
    __syncwarp();
    #pragma unroll
    for (int j = 0; j < 8; j++) { a0[j] = na0[j]; b0[j] = nb0[j];
                                  a1[j] = na1[j]; b1[j] = nb1[j]; }

    // ---- Stage 2: radix-8 over j1; twiddle (W^(8*j0))^h1 ----
    dft8(a0); dft8(b0); twiddle_chain2(a0, b0, base2);
    dft8(a1); dft8(b1); twiddle_chain2(a1, b1, base2);

    // ---- Exchange 2, half 0 (store h=0..3; gather columns c0: h1=q0<=3) ----
    #pragma unroll
    for (int h = 0; h < 4; h++) {
        buf[j0 * P2 + h * 8 + q0]     = make_float4(a0[h].x, a0[h].y, b0[h].x, b0[h].y);
        buf[j0 * P2 + h * 8 + q0 + 4] = make_float4(a1[h].x, a1[h].y, b1[h].x, b1[h].y);
    }
    __syncwarp();
    #pragma unroll
    for (int j = 0; j < 8; j++) {
        float4 u = buf[j * P2 + c0];
        na0[j] = make_float2(u.x, u.y);
        nb0[j] = make_float2(u.z, u.w);
    }
    __syncwarp();
    // ---- Exchange 2, half 1 (store h=4..7; gather columns c1: h1 in 4..7) ----
    #pragma unroll
    for (int h = 4; h < 8; h++) {
        buf[j0 * P2 + (h - 4) * 8 + q0]     = make_float4(a0[h].x, a0[h].y, b0[h].x, b0[h].y);
        buf[j0 * P2 + (h - 4) * 8 + q0 + 4] = make_float4(a1[h].x, a1[h].y, b1[h].x, b1[h].y);
    }
    __syncwarp();
    #pragma unroll
    for (int j = 0; j < 8; j++) {
        float4 u = buf[j * P2 + c0];            // (c1-32) == c0
        na1[j] = make_float2(u.x, u.y);
        nb1[j] = make_float2(u.z, u.w);
    }
    // no trailing syncwarp needed: buffer reused only after next launch-phase

    // ---- Stage 3: radix-8 over j0 ----
    dft8(na0); dft8(nb0);
    dft8(na1); dft8(nb1);

    // output h = h0*64 + c  (fully coalesced)
    if (actA) {
        float2* orow = out + (size_t)rowA * 512;
        #pragma unroll
        for (int h0 = 0; h0 < 8; h0++) {
            orow[h0 * 64 + c0] = na0[h0];
            orow[h0 * 64 + c1] = na1[h0];
        }
    }
    if (actB) {
        float2* orow = out + (size_t)rowB * 512;
        #pragma unroll
        for (int h0 = 0; h0 < 8; h0++) {
            orow[h0 * 64 + c0] = nb0[h0];
            orow[h0 * 64 + c1] = nb1[h0];
        }
    }
}

extern "C" void kernel_launch(void* const* d_in, const int* in_sizes, int n_in,
                              void* d_out, int out_size)
{
    const float* xre = (const float*)d_in[0];
    const float* xim = (const float*)d_in[1];
    const float* wre = (const float*)d_in[2];
    const float* wim = (const float*)d_in[3];
    float2* out = (float2*)d_out;

    const int nrows = in_sizes[0] / 512;            // 32768
    const int rows_per_cta = WARPS_PER_CTA * 2;     // 8
    const int grid = (nrows + rows_per_cta - 1) / rows_per_cta;   // 4096
    fft512_kernel<<<grid, CTA_THREADS>>>(xre, xim, wre, wim, out, nrows);
}

// round 16
// speedup vs baseline: 1.4241x; 1.0156x over previous
#include <cuda_runtime.h>

// Range_Fourier_Net: y = DFT_512(x) per row, complex, output stacked (re, im).
// Radix-8^3 FFT, exact twiddles from row 1 of the provided DFT weight matrix.
//
// R16 = R15 (adjacent-column ownership: thread owns columns {2*lane, 2*lane+1}
// -> 32x LDG.64 loads, 16x STG.128 stores) with the exchange-2 slot-aliasing
// bug FIXED: pitch 67 -> 71 (inner term h2*9+j0 ranges 0..70, so 67 aliased
// distinct (h1,h2,j0) triples onto one slot; 71 is collision-free and its
// bank pattern (71 = 7 mod 8) is conflict-free for .128 in both directions).
//
// Bank/uniqueness analysis (.128, 8-lane phases, bank = 4*slot mod 32):
//  ex1 store  slot = h*68 + (col>>1) + 32*(col&1)  -> 4*lane per phase   OK
//  ex1 gather slot = g*68 + j1*4 + m (+32)         -> 16g+4m distinct    OK
//  ex2 store  slot = h1*71 + g*9 + j0              -> 7h+g+2m distinct   OK
//  ex2 gather slot = g*71 + h2*9 + j              -> 7g+2m+j distinct   OK
//  ex2 uniqueness: g*9 + j0 <= 70 < 71                                   OK

#define WARPS_PER_CTA 4
#define CTA_THREADS (WARPS_PER_CTA * 32)
#define PE1 68
#define PE2 71
#define QE2 9
#define BUF_LEN 568   // ex1 max 7*68+63=539; ex2 max 7*71+70=567

__device__ __forceinline__ float2 cadd(float2 a, float2 b) {
    return make_float2(a.x + b.x, a.y + b.y);
}
__device__ __forceinline__ float2 csub(float2 a, float2 b) {
    return make_float2(a.x - b.x, a.y - b.y);
}
__device__ __forceinline__ float2 cmul(float2 a, float2 b) {
    return make_float2(fmaf(a.x, b.x, -a.y * b.y), fmaf(a.x, b.y, a.y * b.x));
}
// multiply by -i  (W8^2)
__device__ __forceinline__ float2 mul_mi(float2 a) { return make_float2(a.y, -a.x); }

// Natural-order 8-point DFT: v[h] = sum_j v_in[j] * W8^{j*h}, W8 = exp(-i*pi/4)
__device__ __forceinline__ void dft8(float2 v[8]) {
    float2 e0 = v[0], e1 = v[2], e2 = v[4], e3 = v[6];
    float2 o0 = v[1], o1 = v[3], o2 = v[5], o3 = v[7];
    float2 t0 = cadd(e0, e2), t1 = csub(e0, e2);
    float2 t2 = cadd(e1, e3), t3 = mul_mi(csub(e1, e3));
    float2 E0 = cadd(t0, t2), E2 = csub(t0, t2);
    float2 E1 = cadd(t1, t3), E3 = csub(t1, t3);
    float2 s0 = cadd(o0, o2), s1 = csub(o0, o2);
    float2 s2 = cadd(o1, o3), s3 = mul_mi(csub(o1, o3));
    float2 O0 = cadd(s0, s2), O2 = csub(s0, s2);
    float2 O1 = cadd(s1, s3), O3 = csub(s1, s3);
    const float S = 0.70710678118654752440f;
    float2 W1 = make_float2(S * (O1.x + O1.y), S * (O1.y - O1.x));
    float2 W2 = mul_mi(O2);
    float2 W3 = make_float2(S * (O3.y - O3.x), -S * (O3.x + O3.y));
    v[0] = cadd(E0, O0); v[4] = csub(E0, O0);
    v[1] = cadd(E1, W1); v[5] = csub(E1, W1);
    v[2] = cadd(E2, W2); v[6] = csub(E2, W2);
    v[3] = cadd(E3, W3); v[7] = csub(E3, W3);
}

// apply base^h (h=1..7) to TWO arrays sharing the same twiddle base
__device__ __forceinline__ void twiddle_chain2(float2 u[8], float2 v[8], float2 base) {
    float2 f = base;
    #pragma unroll
    for (int h = 1; h < 8; h++) {
        u[h] = cmul(u[h], f);
        v[h] = cmul(v[h], f);
        if (h < 7) f = cmul(f, base);
    }
}

__global__ __launch_bounds__(CTA_THREADS, 4)
void fft512_kernel(const float* __restrict__ xre, const float* __restrict__ xim,
                   const float* __restrict__ wre, const float* __restrict__ wim,
                   float2* __restrict__ out, int nrows)
{
    // per warp: float4 scratch; element = (Are, Aim, Bre, Bim) for one column
    __shared__ float4 buf_s[WARPS_PER_CTA][BUF_LEN];   // 4*568*16 = 36,352 B

    const int tid  = threadIdx.x;
    const int wid  = tid >> 5;
    const int lane = tid & 31;
    const int m    = lane & 3;       // low bits
    const int g    = lane >> 2;      // group 0..7
    const int u0   = 2 * lane;       // even owned column
    const int j0e  = 2 * m;          // even stage-2 j0
    float4* __restrict__ buf = buf_s[wid];

    const int rowA = (blockIdx.x * WARPS_PER_CTA + wid) * 2;
    const int rowB = rowA + 1;
    const bool actA = rowA < nrows;
    const bool actB = rowB < nrows;

    // exact base twiddles from DFT-matrix row 1: W512^k = w[512+k]
    const float2 base1a = make_float2(__ldg(&wre[512 + u0]),     __ldg(&wim[512 + u0]));
    const float2 base1b = make_float2(__ldg(&wre[512 + u0 + 1]), __ldg(&wim[512 + u0 + 1]));
    const float2 base2a = make_float2(__ldg(&wre[512 + 8 * j0e]),     __ldg(&wim[512 + 8 * j0e]));
    const float2 base2b = make_float2(__ldg(&wre[512 + 8 * j0e + 8]), __ldg(&wim[512 + 8 * j0e + 8]));

    // ---- front-batched vector loads: 32 LDG.64 in flight ----
    // a0/a1: row A columns u0 / u0+1 ; b0/b1: row B
    float2 a0[8], a1[8], b0[8], b1[8];
    {
        const float2 z2 = make_float2(0.f, 0.f);
        const float* xrA = xre + (size_t)rowA * 512;
        const float* xiA = xim + (size_t)rowA * 512;
        const float* xrB = xrA + 512;
        const float* xiB = xiA + 512;
        float2 rA[8], iA[8], rB[8], iB[8];
        #pragma unroll
        for (int j = 0; j < 8; j++)
            rA[j] = actA ? *(const float2*)&xrA[64 * j + u0] : z2;
        #pragma unroll
        for (int j = 0; j < 8; j++)
            iA[j] = actA ? *(const float2*)&xiA[64 * j + u0] : z2;
        #pragma unroll
        for (int j = 0; j < 8; j++)
            rB[j] = actB ? *(const float2*)&xrB[64 * j + u0] : z2;
        #pragma unroll
        for (int j = 0; j < 8; j++)
            iB[j] = actB ? *(const float2*)&xiB[64 * j + u0] : z2;
        #pragma unroll
        for (int j = 0; j < 8; j++) {
            a0[j] = make_float2(rA[j].x, iA[j].x);
            a1[j] = make_float2(rA[j].y, iA[j].y);
            b0[j] = make_float2(rB[j].x, iB[j].x);
            b1[j] = make_float2(rB[j].y, iB[j].y);
        }
    }

    // ---- Stage 1: radix-8 over j2 (stride 64); twiddle (W^col)^h2 ----
    dft8(a0); dft8(b0); twiddle_chain2(a0, b0, base1a);
    dft8(a1); dft8(b1); twiddle_chain2(a1, b1, base1b);

    // ---- Exchange 1: slot = h*68 + (col>>1) + 32*(col&1) ----
    #pragma unroll
    for (int h = 0; h < 8; h++) {
        buf[h * PE1 + lane]      = make_float4(a0[h].x, a0[h].y, b0[h].x, b0[h].y);
        buf[h * PE1 + 32 + lane] = make_float4(a1[h].x, a1[h].y, b1[h].x, b1[h].y);
    }
    __syncwarp();
    // gather: stage-2 col s0 = (h2=g, j0=j0e): stage-1 col t = j1*8+j0e (even),
    // elem g -> slot g*68 + (t>>1) = g*68 + j1*4 + m ; s1 (j0e+1, odd): +32
    #pragma unroll
    for (int j1 = 0; j1 < 8; j1++) {
        float4 u = buf[g * PE1 + j1 * 4 + m];
        float4 v = buf[g * PE1 + 32 + j1 * 4 + m];
        a0[j1] = make_float2(u.x, u.y);  b0[j1] = make_float2(u.z, u.w);
        a1[j1] = make_float2(v.x, v.y);  b1[j1] = make_float2(v.z, v.w);
    }
    __syncwarp();

    // ---- Stage 2: radix-8 over j1; twiddle (W^(8*j0))^h1 ----
    dft8(a0); dft8(b0); twiddle_chain2(a0, b0, base2a);
    dft8(a1); dft8(b1); twiddle_chain2(a1, b1, base2b);

    // ---- Exchange 2: slot = h1*71 + h2*9 + j0 ; here h2 = g, j0 = j0e/j0e+1 ----
    #pragma unroll
    for (int h = 0; h < 8; h++) {
        buf[h * PE2 + g * QE2 + j0e]     = make_float4(a0[h].x, a0[h].y, b0[h].x, b0[h].y);
        buf[h * PE2 + g * QE2 + j0e + 1] = make_float4(a1[h].x, a1[h].y, b1[h].x, b1[h].y);
    }
    __syncwarp();
    // gather: stage-3 col f0 = 2*lane = (h1=g, h2=j0e): needs stage-2 col
    // (h2, j0) elem h1=g for j0 = 0..7 -> slot g*71 + j0e*9 + j ; f1: h2=j0e+1
    #pragma unroll
    for (int j = 0; j < 8; j++) {
        float4 u = buf[g * PE2 + j0e * QE2 + j];
        float4 v = buf[g * PE2 + (j0e + 1) * QE2 + j];
        a0[j] = make_float2(u.x, u.y);  b0[j] = make_float2(u.z, u.w);
        a1[j] = make_float2(v.x, v.y);  b1[j] = make_float2(v.z, v.w);
    }

    // ---- Stage 3: radix-8 over j0 ----
    dft8(a0); dft8(b0);
    dft8(a1); dft8(b1);

    // output h = h0*64 + f, f0 = 2*lane, f1 = 2*lane+1 adjacent -> STG.128
    if (actA) {
        float4* orow = (float4*)(out + (size_t)rowA * 512);
        #pragma unroll
        for (int h0 = 0; h0 < 8; h0++)
            orow[h0 * 32 + lane] = make_float4(a0[h0].x, a0[h0].y, a1[h0].x, a1[h0].y);
    }
    if (actB) {
        float4* orow = (float4*)(out + (size_t)rowB * 512);
        #pragma unroll
        for (int h0 = 0; h0 < 8; h0++)
            orow[h0 * 32 + lane] = make_float4(b0[h0].x, b0[h0].y, b1[h0].x, b1[h0].y);
    }
}

extern "C" void kernel_launch(void* const* d_in, const int* in_sizes, int n_in,
                              void* d_out, int out_size)
{
    const float* xre = (const float*)d_in[0];
    const float* xim = (const float*)d_in[1];
    const float* wre = (const float*)d_in[2];
    const float* wim = (const float*)d_in[3];
    float2* out = (float2*)d_out;

    const int nrows = in_sizes[0] / 512;            // 32768
    const int rows_per_cta = WARPS_PER_CTA * 2;     // 8
    const int grid = (nrows + rows_per_cta - 1) / rows_per_cta;   // 4096
    fft512_kernel<<<grid, CTA_THREADS>>>(xre, xim, wre, wim, out, nrows);
}